// round 8
// baseline (speedup 1.0000x reference)
#include <cuda_runtime.h>
#include <cuda_fp16.h>
#include <math.h>
#include <stdint.h>

// Glm4vMoeTextTopkRouter R7:
//  - kernel 1: one-time split of weight into fp16 hi/lo "smem image" layout (swizzled, per
//    64-k chunk) in a __device__ buffer -> main loop stages B via linear cp.async.
//  - kernel 2: BM=128 x NE=128 tile, 8 warps (m32n64 each), fp16 split-precision mma.sync
//    (HH into acc, HL+LH into cor), flushed every 4 chunks into a smem fp32 accumulator
//    (kills TC C-add truncation chain), fused sigmoid + bias top-8 + normalize.

#define HD 4096
#define NE 128
#define TOPK 8
#define BM 128
#define KC 64
#define NCH (HD / KC)        // 64
#define NT 256               // 8 warps

#define LO_SCALE 2048.0f
#define LO_INV   (1.0f / 2048.0f)

#define SW128(o) ((uint32_t)(o) ^ ((((uint32_t)(o)) >> 3) & 0x70))

// B image: per chunk [hi 16KB][lo 16KB]
#define BIMG_CHUNK 32768
__device__ __align__(16) char gBconv[NCH * BIMG_CHUNK];   // 2 MB

// ---- smem layout (dynamic) ----
#define OFF_BIAS  0                       // 128 f32
#define OFF_SUM   512                     // 128 x 129 f32 = 66048 B
#define OFF_STAGE (512 + 66048)           // 66560
#define A_MAT 16384                       // 128 rows x 128B
#define STGB 65536                        // A_hi|A_lo|B_hi|B_lo
#define SMEM_TOTAL (OFF_STAGE + 2 * STGB) // 197632

__device__ __forceinline__ uint32_t smem_u32(const void* p) {
    uint32_t a;
    asm("{ .reg .u64 t; cvta.to.shared.u64 t, %1; cvt.u32.u64 %0, t; }" : "=r"(a) : "l"(p));
    return a;
}

__device__ __forceinline__ void ldsm_x4(uint32_t addr, uint32_t* r) {
    asm volatile("ldmatrix.sync.aligned.m8n8.x4.shared.b16 {%0,%1,%2,%3}, [%4];"
                 : "=r"(r[0]), "=r"(r[1]), "=r"(r[2]), "=r"(r[3]) : "r"(addr));
}

__device__ __forceinline__ void mma16816(float* c, const uint32_t* a, uint32_t b0, uint32_t b1) {
    asm volatile("mma.sync.aligned.m16n8k16.row.col.f32.f16.f16.f32 "
                 "{%0,%1,%2,%3}, {%4,%5,%6,%7}, {%8,%9}, {%0,%1,%2,%3};"
                 : "+f"(c[0]), "+f"(c[1]), "+f"(c[2]), "+f"(c[3])
                 : "r"(a[0]), "r"(a[1]), "r"(a[2]), "r"(a[3]), "r"(b0), "r"(b1));
}

__device__ __forceinline__ void cp_async16(uint32_t smem_dst, const void* gsrc) {
    asm volatile("cp.async.cg.shared.global [%0], [%1], 16;"
                 :: "r"(smem_dst), "l"(gsrc) : "memory");
}
#define CP_COMMIT() asm volatile("cp.async.commit_group;" ::: "memory")
#define CP_WAIT0()  asm volatile("cp.async.wait_group 0;" ::: "memory")

__device__ __forceinline__ uint32_t h2u(half2 h) { return *reinterpret_cast<uint32_t*>(&h); }

__device__ __forceinline__ void store_split(char* hi_p, char* lo_p, float4 v) {
    half2 h0 = __floats2half2_rn(v.x, v.y);
    half2 h1 = __floats2half2_rn(v.z, v.w);
    float2 f0 = __half22float2(h0);
    float2 f1 = __half22float2(h1);
    half2 l0 = __floats2half2_rn((v.x - f0.x) * LO_SCALE, (v.y - f0.y) * LO_SCALE);
    half2 l1 = __floats2half2_rn((v.z - f1.x) * LO_SCALE, (v.w - f1.y) * LO_SCALE);
    *(uint2*)hi_p = make_uint2(h2u(h0), h2u(h1));
    *(uint2*)lo_p = make_uint2(h2u(l0), h2u(l1));
}

// verified ldmatrix address maps (128B pitch, SW128)
__device__ __forceinline__ uint32_t a_addr(uint32_t base, int l, int mb, int kb) {
    int row = mb + (l & 7) + ((l >> 3) & 1) * 8;
    int colb = (kb + ((l >> 4) << 3)) * 2;
    return base + SW128(row * 128 + colb);
}
__device__ __forceinline__ uint32_t b_addr(uint32_t base, int l, int nb, int kb) {
    int row = nb + (l & 7) + ((l >> 4) << 3);
    int colb = (kb + (((l >> 3) & 1) << 3)) * 2;
    return base + SW128(row * 128 + colb);
}

// ---- kernel 1: build B image (runs once per launch, ~2MB of work) ----
__global__ void prep_b_kernel(const float* __restrict__ weight) {
    const int e = blockIdx.x;          // expert 0..127
    const int k = threadIdx.x * 4;     // 1024 threads, one float4 each
    float4 v = *(const float4*)(weight + (size_t)e * HD + k);
    const int chunk = k >> 6;
    const int col = k & 63;
    uint32_t off = SW128((uint32_t)(e * 128 + col * 2));
    char* base = gBconv + (size_t)chunk * BIMG_CHUNK;
    store_split(base + off, base + 16384 + off, v);
}

// ---- kernel 2: main fused router ----
__global__ __launch_bounds__(NT, 1)
void router_mma_kernel(const float* __restrict__ hidden,
                       const float* __restrict__ bias,
                       float* __restrict__ out, int T)
{
    extern __shared__ char smem[];
    const uint32_t sbase = smem_u32(smem);
    const int tid = threadIdx.x;
    const int wid = tid >> 5, lid = tid & 31;
    const int m0 = blockIdx.x * BM;

    float* sumsm = (float*)(smem + OFF_SUM);
    if (tid < NE) ((float*)(smem + OFF_BIAS))[tid] = bias[tid];
    for (int i = tid; i < 128 * 129; i += NT) sumsm[i] = 0.0f;

    const int arow = tid >> 4;   // 0..15
    const int c4   = tid & 15;
    const float* aBase = hidden + (size_t)(m0 + arow) * HD + c4 * 4;

    // warp grid 4m x 2n; warp tile m32 x n64
    const int mb = (wid >> 1) * 32;
    const int nb = (wid & 1) * 64;

    // frag f = m*8 + ng*2 + r   (m:0..1 m16 halves, ng:0..3 n16 groups, r:0..1 n8 within)
    float acc[16][4], cor[16][4];
#pragma unroll
    for (int f = 0; f < 16; f++)
#pragma unroll
        for (int q = 0; q < 4; q++) { acc[f][q] = 0.0f; cor[f][q] = 0.0f; }

    float4 va[8];
#pragma unroll
    for (int i = 0; i < 8; i++) va[i] = *(const float4*)(aBase + (size_t)(i * 16) * HD);

    // prologue: B chunk 0 via cp.async (linear, swizzle pre-baked)
    {
        uint32_t dst = sbase + OFF_STAGE + 2 * A_MAT + tid * 128;
        const char* src = gBconv + (size_t)tid * 128;
#pragma unroll
        for (int i = 0; i < 8; i++) cp_async16(dst + i * 16, src + i * 16);
        CP_COMMIT();
    }
    __syncthreads();   // sum/bias init visible

    for (int c = 0; c < NCH; ++c) {
        char* stg = smem + OFF_STAGE + (c & 1) * STGB;
        // STS A(c): hi/lo split (writes buf(c&1); mma(c-2) readers retired before BAR(c-1))
#pragma unroll
        for (int i = 0; i < 8; i++) {
            uint32_t off = SW128((uint32_t)((i * 16 + arow) * 128 + c4 * 8));
            store_split(stg + off, stg + A_MAT + off, va[i]);
        }
        if (c + 1 < NCH) {
            const float* ap = aBase + (size_t)(c + 1) * KC;
#pragma unroll
            for (int i = 0; i < 8; i++) va[i] = *(const float4*)(ap + (size_t)(i * 16) * HD);
        }
        CP_WAIT0();        // B(c) landed
        __syncthreads();   // A(c)+B(c) visible; mma(c-1) retired CTA-wide

        // issue B(c+1) AFTER the barrier: its buffer was last read by mma(c-1), now retired
        if (c + 1 < NCH) {
            uint32_t dst = sbase + OFF_STAGE + ((c + 1) & 1) * STGB + 2 * A_MAT + tid * 128;
            const char* src = gBconv + (size_t)(c + 1) * BIMG_CHUNK + (size_t)tid * 128;
#pragma unroll
            for (int i = 0; i < 8; i++) cp_async16(dst + i * 16, src + i * 16);
            CP_COMMIT();
        }

        const uint32_t sA_hi = sbase + OFF_STAGE + (c & 1) * STGB;
        const uint32_t sA_lo = sA_hi + A_MAT;
        const uint32_t sB_hi = sA_hi + 2 * A_MAT;
        const uint32_t sB_lo = sA_hi + 3 * A_MAT;

#pragma unroll
        for (int ks = 0; ks < 4; ks++) {
            const int kb = ks * 16;
            uint32_t ah[2][4], al[2][4], bh[4][4], bl[4][4];
            ldsm_x4(a_addr(sA_hi, lid, mb,      kb), ah[0]);
            ldsm_x4(a_addr(sA_hi, lid, mb + 16, kb), ah[1]);
            ldsm_x4(a_addr(sA_lo, lid, mb,      kb), al[0]);
            ldsm_x4(a_addr(sA_lo, lid, mb + 16, kb), al[1]);
#pragma unroll
            for (int ng = 0; ng < 4; ng++) {
                ldsm_x4(b_addr(sB_hi, lid, nb + ng * 16, kb), bh[ng]);
                ldsm_x4(b_addr(sB_lo, lid, nb + ng * 16, kb), bl[ng]);
            }
            // HH pass
#pragma unroll
            for (int m = 0; m < 2; m++)
#pragma unroll
                for (int ng = 0; ng < 4; ng++) {
                    mma16816(acc[m * 8 + ng * 2 + 0], ah[m], bh[ng][0], bh[ng][1]);
                    mma16816(acc[m * 8 + ng * 2 + 1], ah[m], bh[ng][2], bh[ng][3]);
                }
            // HL pass
#pragma unroll
            for (int m = 0; m < 2; m++)
#pragma unroll
                for (int ng = 0; ng < 4; ng++) {
                    mma16816(cor[m * 8 + ng * 2 + 0], ah[m], bl[ng][0], bl[ng][1]);
                    mma16816(cor[m * 8 + ng * 2 + 1], ah[m], bl[ng][2], bl[ng][3]);
                }
            // LH pass (same cor bank; 16 instructions after matching HL -> no tight RAW)
#pragma unroll
            for (int m = 0; m < 2; m++)
#pragma unroll
                for (int ng = 0; ng < 4; ng++) {
                    mma16816(cor[m * 8 + ng * 2 + 0], al[m], bh[ng][0], bh[ng][1]);
                    mma16816(cor[m * 8 + ng * 2 + 1], al[m], bh[ng][2], bh[ng][3]);
                }
        }

        // flush TC accumulators into smem fp32 sum every 4 chunks (breaks TC C-add chain)
        if ((c & 3) == 3) {
#pragma unroll
            for (int m = 0; m < 2; m++)
#pragma unroll
                for (int ng = 0; ng < 4; ng++)
#pragma unroll
                    for (int r = 0; r < 2; r++) {
                        const int f = m * 8 + ng * 2 + r;
#pragma unroll
                        for (int q = 0; q < 4; q++) {
                            const int row = mb + m * 16 + (lid >> 2) + (q >> 1) * 8;
                            const int col = nb + ng * 16 + r * 8 + (lid & 3) * 2 + (q & 1);
                            sumsm[row * 129 + col] += fmaf(cor[f][q], LO_INV, acc[f][q]);
                            acc[f][q] = 0.0f; cor[f][q] = 0.0f;
                        }
                    }
        }
    }

    __syncthreads();   // all flushes done

    // sigmoid in place over the sum scoreboard
    for (int idx = tid; idx < BM * NE; idx += NT) {
        const int row = idx >> 7, col = idx & 127;
        float v = sumsm[row * 129 + col];
        sumsm[row * 129 + col] = 1.0f / (1.0f + expf(-v));
    }
    __syncthreads();

    // top-8 per token (threads 0..127); strict '>' => lowest-index ties like lax.top_k
    if (tid < BM) {
        const int gtok = m0 + tid;
        float* row = sumsm + tid * 129;
        const float* sb = (const float*)(smem + OFF_BIAS);
        float w[TOPK]; int idx[TOPK]; float ssum = 0.0f;
#pragma unroll
        for (int p = 0; p < TOPK; p++) {
            float mx = -1e30f; int mi = 0;
#pragma unroll 16
            for (int e = 0; e < NE; e++) {
                float v = row[e] + sb[e];
                if (v > mx) { mx = v; mi = e; }
            }
            idx[p] = mi;
            w[p] = row[mi];
            row[mi] = -3e30f;
            ssum += w[p];
        }
        const float inv = 1.0f / (ssum + 1e-20f);
        float* oi = out + (size_t)gtok * TOPK;
        float* ow = out + (size_t)T * TOPK + (size_t)gtok * TOPK;
#pragma unroll
        for (int p = 0; p < TOPK; p++) {
            oi[p] = (float)idx[p];
            ow[p] = w[p] * inv;
        }
    }
}

extern "C" void kernel_launch(void* const* d_in, const int* in_sizes, int n_in,
                              void* d_out, int out_size)
{
    const float* hidden = (const float*)d_in[0];
    const float* weight = (const float*)d_in[1];
    const float* bias   = (const float*)d_in[2];
    const int T = in_sizes[0] / HD;   // 32768

    prep_b_kernel<<<NE, HD / 4>>>(weight);   // 128 blocks x 1024 threads

    cudaFuncSetAttribute(router_mma_kernel,
                         cudaFuncAttributeMaxDynamicSharedMemorySize, SMEM_TOTAL);
    router_mma_kernel<<<T / BM, NT, SMEM_TOTAL>>>(hidden, bias, (float*)d_out, T);
}